// round 8
// baseline (speedup 1.0000x reference)
#include <cuda_runtime.h>
#include <cuda_bf16.h>

// SMorph layer: y = softdilate(x,k1) + softerode(x,k2) + bias
// Factorized via exp(p+k)=exp(p)exp(k):
//   den = conv((e,em),(A1,A2))  num = conv((pe,pem),(A1,A2)) + conv((e,em),(B1,B2))
//   out = num.x/den.x + num.y/den.y + bias   [f32x2 lanes: dilate|erode]
//
// Round 8: single merged pass. 63x7 tile, 512 thr = 8 chunks x 64 lanes,
// 2 filters per chunk in ONE sweep (was 2 passes of 1) -> map LDS halved
// (648 -> 324 wavefronts/warp). Register budget raised to 128 via 1 CTA/SM
// (rounds 5 vs 6 proved occupancy 20% vs 40% is perf-neutral here):
// acc 56 + hoisted weights 24 + depth-3 pbuf 12 + misc ~= 107 regs.
// Prologue rewritten warp-owns-row (no div/mod in the hot path).

#define BATCH 8
#define CIN   3
#define HIN   128
#define WIN   128
#define FOUT  16
#define HOUT  126
#define WOUT  126

#define TW    63           // tile width  (cols)
#define TH    7            // tile height (rows)
#define TINW  65           // TW + 2 halo
#define TINH  9            // TH + 2 halo
#define NTHREADS 512

__device__ __forceinline__ void ffma2(unsigned long long& d,
                                      unsigned long long a,
                                      unsigned long long b)
{
    asm("fma.rn.f32x2 %0, %1, %2, %0;" : "+l"(d) : "l"(a), "l"(b));
}

__device__ __forceinline__ float2 unpack2(unsigned long long v)
{
    float2 r;
    asm("mov.b64 {%0, %1}, %2;" : "=f"(r.x), "=f"(r.y) : "l"(v));
    return r;
}

__global__ __launch_bounds__(NTHREADS, 1)
void smorph_kernel(const float* __restrict__ x,
                   const float* __restrict__ k1,
                   const float* __restrict__ k2,
                   const float* __restrict__ bias,
                   float* __restrict__ out)
{
    __shared__ float4 sMap[CIN][TINH][TINW];   // (e,em,pe,pem) 3*9*65*16 = 28080 B
    __shared__ float4 sW[27][FOUT];            // (A1,A2,B1,B2)          6912 B
    __shared__ float  sBias[FOUT];

    const int tid  = threadIdx.x;
    const int warp = tid >> 5;
    const int lane = tid & 31;
    const int fc   = tid >> 6;                 // filter chunk 0..7 -> filters 2fc,2fc+1
    const int col  = tid & 63;                 // 0..63 (63 = idle lane)
    const int colc = min(col, TW - 1);         // keep idle lane's loads in-range
    const int bx   = blockIdx.x, by = blockIdx.y, b = blockIdx.z;
    const int gx0  = bx * TW,  gy0 = by * TH;

    // ---- Weight precompute: j = c*9 + kh*3 + kw ; mem idx ((kh*3+kw)*3+c)*16+f
    if (tid < FOUT) sBias[tid] = bias[tid];
    for (int i = tid; i < 27 * FOUT; i += NTHREADS) {
        int j = i >> 4, f = i & 15;
        int c = j / 9, r = j - c * 9;
        int gi = (r * 3 + c) * FOUT + f;
        float w1 = k1[gi], w2 = k2[gi];
        float a1 = __expf(w1), a2 = __expf(w2);
        sW[j][f] = make_float4(a1, a2, w1 * a1, w2 * a2);
    }

    // ---- Tile load + map precompute, warp-owns-row (27 (c,r) rows over 16
    // warps; lanes stride the 65 columns). Always in-bounds.
    for (int row = warp; row < CIN * TINH; row += NTHREADS / 32) {
        int c = row / 9;                       // 0..2 (mulhi, cheap)
        int r = row - c * 9;
        const float* src = &x[((b * CIN + c) * HIN + (gy0 + r)) * WIN + gx0];
        float4* dst = &sMap[c][r][0];
        for (int cc = lane; cc < TINW; cc += 32) {
            float v  = src[cc];
            float e  = __expf(v);
            float em = __expf(-v);
            dst[cc] = make_float4(e, em, v * e, -v * em);
        }
    }
    __syncthreads();

    const int ow = gx0 + col;
    const int f0 = fc * 2;

    // ---- Single merged sweep, 2 filters per chunk.
    unsigned long long den[2][TH], num[2][TH];
#pragma unroll
    for (int fi = 0; fi < 2; fi++)
#pragma unroll
        for (int p = 0; p < TH; p++) { den[fi][p] = 0ull; num[fi][p] = 0ull; }

#pragma unroll 1
    for (int c = 0; c < CIN; c++) {
#pragma unroll
        for (int kw = 0; kw < 3; kw++) {
            // Hoist this chunk's 2 filters x 3 kh weights for (c,kw).
            ulonglong2 w[3][2];
#pragma unroll
            for (int kh = 0; kh < 3; kh++) {
#pragma unroll
                for (int fi = 0; fi < 2; fi++)
                    w[kh][fi] = *reinterpret_cast<const ulonglong2*>(
                                    &sW[c * 9 + kh * 3 + kw][f0 + fi]);
            }

            const ulonglong2* sp = reinterpret_cast<const ulonglong2*>(
                                       &sMap[c][0][colc + kw]);

            // Depth-3 pipelined row stream; row rr feeds px = rr-kh.
            ulonglong2 pbuf[3];
            pbuf[0] = sp[0 * TINW];
            pbuf[1] = sp[1 * TINW];
            pbuf[2] = sp[2 * TINW];
#pragma unroll
            for (int rr = 0; rr < TINH; rr++) {
                const ulonglong2 p = pbuf[rr % 3];
                if (rr + 3 < TINH)
                    pbuf[rr % 3] = sp[(rr + 3) * TINW];
#pragma unroll
                for (int kh = 0; kh < 3; kh++) {
                    const int px = rr - kh;
                    if (px >= 0 && px < TH) {
#pragma unroll
                        for (int fi = 0; fi < 2; fi++) {
                            ffma2(den[fi][px], p.x, w[kh][fi].x);
                            ffma2(num[fi][px], p.y, w[kh][fi].x);
                            ffma2(num[fi][px], p.x, w[kh][fi].y);
                        }
                    }
                }
            }
        }
    }

    // ---- Epilogue: 2 filters x 7 pixels
    if (col < TW) {
#pragma unroll
        for (int fi = 0; fi < 2; fi++) {
            const int f = f0 + fi;
            const float bz = sBias[f];
            float* dst = &out[((b * FOUT + f) * HOUT + gy0) * WOUT + ow];
#pragma unroll
            for (int px = 0; px < TH; px++) {
                float2 n = unpack2(num[fi][px]);
                float2 d = unpack2(den[fi][px]);
                dst[px * WOUT] =
                    __fdividef(n.x, d.x) + __fdividef(n.y, d.y) + bz;
            }
        }
    }
}

extern "C" void kernel_launch(void* const* d_in, const int* in_sizes, int n_in,
                              void* d_out, int out_size)
{
    const float* x    = (const float*)d_in[0];
    const float* k1   = (const float*)d_in[1];
    const float* k2   = (const float*)d_in[2];
    const float* bias = (const float*)d_in[3];
    float* out = (float*)d_out;

    dim3 grid(WOUT / TW,    // 2
              HOUT / TH,    // 18
              BATCH);       // 8
    smorph_kernel<<<grid, NTHREADS>>>(x, k1, k2, bias, out);
}

// round 9
// speedup vs baseline: 1.0894x; 1.0894x over previous
#include <cuda_runtime.h>
#include <cuda_bf16.h>

// SMorph layer: y = softdilate(x,k1) + softerode(x,k2) + bias
// Factorized via exp(p+k)=exp(p)exp(k):
//   den = conv((e,em),(A1,A2))  num = conv((pe,pem),(A1,A2)) + conv((e,em),(B1,B2))
//   out = num.x/den.x + num.y/den.y + bias   [f32x2 lanes: dilate|erode]
//
// Round 9: the kernel is fp32-FMA-LANE bound (329M FMAs ~ 19.3us floor;
// r5/r6/r7 identical at 22.6 despite occupancy/MLP/LDS changes). Revert to
// the r6 champion (63x7 tile, grid 288 single wave, 512thr = 8 chunks x 64
// lanes, 1 filter/pass x 2 passes, 64-reg 2-CTA/SM budget) and harvest the
// ~13% overhead band: warp-owns-row prologue (no div/mod), no pbuf pipeline
// (r7 proved neutral; frees regs for ptxas scheduling), hoisted base
// pointers, tightened epilogue addressing.

#define BATCH 8
#define CIN   3
#define HIN   128
#define WIN   128
#define FOUT  16
#define HOUT  126
#define WOUT  126

#define TW    63           // tile width  (cols)
#define TH    7            // tile height (rows)
#define TINW  65           // TW + 2 halo
#define TINH  9            // TH + 2 halo
#define NTHREADS 512

__device__ __forceinline__ void ffma2(unsigned long long& d,
                                      unsigned long long a,
                                      unsigned long long b)
{
    asm("fma.rn.f32x2 %0, %1, %2, %0;" : "+l"(d) : "l"(a), "l"(b));
}

__device__ __forceinline__ float2 unpack2(unsigned long long v)
{
    float2 r;
    asm("mov.b64 {%0, %1}, %2;" : "=f"(r.x), "=f"(r.y) : "l"(v));
    return r;
}

__global__ __launch_bounds__(NTHREADS, 2)
void smorph_kernel(const float* __restrict__ x,
                   const float* __restrict__ k1,
                   const float* __restrict__ k2,
                   const float* __restrict__ bias,
                   float* __restrict__ out)
{
    __shared__ float4 sMap[CIN][TINH][TINW];   // (e,em,pe,pem) 3*9*65*16 = 28080 B
    __shared__ float4 sW[27][FOUT];            // (A1,A2,B1,B2)          6912 B
    __shared__ float  sBias[FOUT];

    const int tid  = threadIdx.x;
    const int warp = tid >> 5;
    const int lane = tid & 31;
    const int fc   = tid >> 6;                 // filter chunk 0..7
    const int col  = tid & 63;                 // 0..63 (63 = idle lane)
    const int colc = min(col, TW - 1);         // keep idle lane's loads in-range
    const int bx   = blockIdx.x, by = blockIdx.y, b = blockIdx.z;
    const int gx0  = bx * TW,  gy0 = by * TH;

    // ---- Weight precompute: j = c*9 + kh*3 + kw ; mem idx ((kh*3+kw)*3+c)*16+f
    if (tid < FOUT) sBias[tid] = bias[tid];
    if (tid < 27 * FOUT) {                     // one element per thread (432<512)
        int j = tid >> 4, f = tid & 15;
        int c = j / 9, r = j - c * 9;
        int gi = (r * 3 + c) * FOUT + f;
        float w1 = k1[gi], w2 = k2[gi];
        float a1 = __expf(w1), a2 = __expf(w2);
        sW[j][f] = make_float4(a1, a2, w1 * a1, w2 * a2);
    }

    // ---- Tile load + map precompute, warp-owns-row: 27 (c,r) rows over 16
    // warps (11 warps do 2 rows); lanes stride the 65 columns. In-bounds by
    // construction (gy0+8 <= 127, gx0+64 <= 127).
    for (int row = warp; row < CIN * TINH; row += NTHREADS / 32) {
        int c = row / 9;
        int r = row - c * 9;
        const float* src = &x[((b * CIN + c) * HIN + (gy0 + r)) * WIN + gx0];
        float4* dst = &sMap[c][r][0];
        for (int cc = lane; cc < TINW; cc += 32) {
            float v  = src[cc];
            float e  = __expf(v);
            float em = __expf(-v);
            dst[cc] = make_float4(e, em, v * e, -v * em);
        }
    }
    __syncthreads();

    const int ow = gx0 + col;

    // ---- Two sequential passes, ONE filter each (acc = 28 regs).
#pragma unroll 1
    for (int pass = 0; pass < 2; pass++) {
        const int f = pass * 8 + fc;           // this pass's filter

        unsigned long long den[TH], num[TH];
#pragma unroll
        for (int p = 0; p < TH; p++) { den[p] = 0ull; num[p] = 0ull; }

#pragma unroll 1
        for (int c = 0; c < CIN; c++) {
#pragma unroll
            for (int kw = 0; kw < 3; kw++) {
                // Hoist this filter's 3 kh-weights for (c,kw).
                const ulonglong2 w0 = *reinterpret_cast<const ulonglong2*>(
                                          &sW[c * 9 + 0 * 3 + kw][f]);
                const ulonglong2 w1 = *reinterpret_cast<const ulonglong2*>(
                                          &sW[c * 9 + 1 * 3 + kw][f]);
                const ulonglong2 w2 = *reinterpret_cast<const ulonglong2*>(
                                          &sW[c * 9 + 2 * 3 + kw][f]);

                const ulonglong2* sp = reinterpret_cast<const ulonglong2*>(
                                           &sMap[c][0][colc + kw]);

                // Stream the 9 rows; row rr feeds px = rr-kh (static under
                // full unroll). Pipe-bound: scheduling handled by ptxas.
#pragma unroll
                for (int rr = 0; rr < TINH; rr++) {
                    const ulonglong2 p = sp[rr * TINW];
                    if (rr <= TH - 1) {                 // kh=0, px=rr
                        ffma2(den[rr],     p.x, w0.x);
                        ffma2(num[rr],     p.y, w0.x);
                        ffma2(num[rr],     p.x, w0.y);
                    }
                    if (rr >= 1 && rr <= TH) {          // kh=1, px=rr-1
                        ffma2(den[rr - 1], p.x, w1.x);
                        ffma2(num[rr - 1], p.y, w1.x);
                        ffma2(num[rr - 1], p.x, w1.y);
                    }
                    if (rr >= 2) {                      // kh=2, px=rr-2
                        ffma2(den[rr - 2], p.x, w2.x);
                        ffma2(num[rr - 2], p.y, w2.x);
                        ffma2(num[rr - 2], p.x, w2.y);
                    }
                }
            }
        }

        // ---- Epilogue for this pass: 1 filter x 7 pixels
        if (col < TW) {
            const float bz = sBias[f];
            float* dst = &out[((b * FOUT + f) * HOUT + gy0) * WOUT + ow];
#pragma unroll
            for (int px = 0; px < TH; px++) {
                float2 n = unpack2(num[px]);
                float2 d = unpack2(den[px]);
                dst[px * WOUT] =
                    __fdividef(n.x, d.x) + __fdividef(n.y, d.y) + bz;
            }
        }
    }
}

extern "C" void kernel_launch(void* const* d_in, const int* in_sizes, int n_in,
                              void* d_out, int out_size)
{
    const float* x    = (const float*)d_in[0];
    const float* k1   = (const float*)d_in[1];
    const float* k2   = (const float*)d_in[2];
    const float* bias = (const float*)d_in[3];
    float* out = (float*)d_out;

    dim3 grid(WOUT / TW,    // 2
              HOUT / TH,    // 18
              BATCH);       // 8
    smorph_kernel<<<grid, NTHREADS>>>(x, k1, k2, bias, out);
}

// round 12
// speedup vs baseline: 1.1429x; 1.0491x over previous
#include <cuda_runtime.h>
#include <cuda_fp16.h>
#include <cstdint>

// SMorph layer on HMMA (mma.sync m16n8k16 f16->f32), plain sm_100 target.
// Factorized via exp(p+k)=exp(p)exp(k):
//   den1=conv(E,A1)  num1=conv(PE,A1)+conv(E,B1)   (A=exp(k), B=k exp(k))
//   den2=conv(EM,A2) num2=conv(PEM,A2)+conv(EM,B2)
//   out = num1/den1 + num2/den2 + bias
// GEMM: D[m=pixel][n=0..63] ; n: [0,16)=den1, [16,32)=num1, [32,48)=den2,
// [48,64)=num2. K per tap = 32 slots: 0-11 map hi (E,PE,EM,PEM x 3c),
// 12-23 map lo (fp16 residual; same weights -> ~22-bit data mantissa),
// 24-31 zero pad. 9 taps = 9 accumulating MMA groups whose A base address
// is shifted by (kh*128+kw) pixels (map rows are full-width 128 px).
//
// A smem: pixel-major, 80 B/pixel (40 halves). 80 mod 128 walks all eight
// 16B banks over 8 consecutive pixels -> conflict-free ldmatrix.
// B smem: [tap][n][k] rows of 80 B, non-trans ldmatrix = b-fragment direct.

#define BATCH 8
#define CIN   3
#define HIN   128
#define WIN   128
#define FOUT  16
#define HOUT  126
#define WOUT  126

#define NT       256
#define ROWS_OUT 2
#define NPX      (4 * 128 + 8)      // 4 input rows + shift-overflow pad = 520
#define APITCH   80                 // bytes per pixel
#define A_BYTES  (NPX * APITCH)     // 41600
#define BPITCH   80                 // bytes per n-row
#define B_TAP    (64 * BPITCH)      // 5120
#define B_BYTES  (9 * B_TAP)        // 46080
#define SMEM_DYN (A_BYTES + B_BYTES)

__device__ __forceinline__ uint32_t smem_u32(const void* p) {
    uint32_t a;
    asm("{ .reg .u64 t; cvta.to.shared.u64 t, %1; cvt.u32.u64 %0, t; }"
        : "=r"(a) : "l"(p));
    return a;
}

__device__ __forceinline__ void ldm4(uint32_t* r, uint32_t addr) {
    asm volatile("ldmatrix.sync.aligned.m8n8.x4.shared.b16 {%0,%1,%2,%3}, [%4];"
                 : "=r"(r[0]), "=r"(r[1]), "=r"(r[2]), "=r"(r[3]) : "r"(addr));
}

__device__ __forceinline__ void mma16816(float* d, const uint32_t* a,
                                         const uint32_t* b) {
    asm volatile(
        "mma.sync.aligned.m16n8k16.row.col.f32.f16.f16.f32 "
        "{%0,%1,%2,%3}, {%4,%5,%6,%7}, {%8,%9}, {%0,%1,%2,%3};"
        : "+f"(d[0]), "+f"(d[1]), "+f"(d[2]), "+f"(d[3])
        : "r"(a[0]), "r"(a[1]), "r"(a[2]), "r"(a[3]), "r"(b[0]), "r"(b[1]));
}

__device__ __forceinline__ uint32_t pkh(__half a, __half b) {
    __half2 h = __halves2half2(a, b);
    return *reinterpret_cast<uint32_t*>(&h);
}

__global__ __launch_bounds__(NT)
void smorph_hmma_kernel(const float* __restrict__ x,
                        const float* __restrict__ k1,
                        const float* __restrict__ k2,
                        const float* __restrict__ bias,
                        float* __restrict__ out)
{
    extern __shared__ char dsm[];
    char* smA = dsm;
    char* smB = dsm + A_BYTES;

    const int tid  = threadIdx.x;
    const int wid  = tid >> 5;
    const int lane = tid & 31;
    const int b    = blockIdx.x;
    const int r0   = blockIdx.y * ROWS_OUT;   // first output row (gy0 too)

    // ---- Phase 1: A map fill (hi/lo fp16) + B zero ------------------------
    for (int px = tid; px < NPX; px += NT) {
        float m[12];
#pragma unroll
        for (int i = 0; i < 12; i++) m[i] = 0.0f;
        if (px < 512) {
            int row = px >> 7, xc = px & 127;
            int gy = r0 + row;                 // r0<=124 -> gy<=127, in-bounds
#pragma unroll
            for (int c = 0; c < CIN; c++) {
                float v  = x[((b * CIN + c) * HIN + gy) * WIN + xc];
                float e  = __expf(v);
                float em = __expf(-v);
                m[c]     = e;
                m[3 + c] = v * e;
                m[6 + c] = em;
                m[9 + c] = -v * em;
            }
        }
        __half h[24];
#pragma unroll
        for (int i = 0; i < 12; i++) {
            h[i] = __float2half_rn(m[i]);
            h[12 + i] = __float2half_rn(m[i] - __half2float(h[i]));
        }
        uint32_t w[20];
#pragma unroll
        for (int j2 = 0; j2 < 12; j2++) w[j2] = pkh(h[2 * j2], h[2 * j2 + 1]);
#pragma unroll
        for (int j2 = 12; j2 < 20; j2++) w[j2] = 0u;          // slots 24-39
        uint4* dst = reinterpret_cast<uint4*>(smA + px * APITCH);
#pragma unroll
        for (int q = 0; q < 5; q++)
            dst[q] = make_uint4(w[4 * q], w[4 * q + 1], w[4 * q + 2], w[4 * q + 3]);
    }
    for (int i = tid; i < B_BYTES / 16; i += NT)
        reinterpret_cast<uint4*>(smB)[i] = make_uint4(0, 0, 0, 0);
    __syncthreads();

    // ---- Phase 2: B weight scatter. k-mem idx ((kh*3+kw)*3+c)*16+f --------
    for (int i = tid; i < 9 * CIN * FOUT; i += NT) {
        int f = i & 15, rest = i >> 4;       // rest = tap*3 + c
        int tap = rest / 3, c = rest - tap * 3;
        int gi = (tap * 3 + c) * FOUT + f;
        float w1 = k1[gi], w2 = k2[gi];
        float a1 = __expf(w1), a2 = __expf(w2);
        float b1 = w1 * a1,   b2 = w2 * a2;
        char* base = smB + tap * B_TAP;
#define BST(n, s, val) \
        *reinterpret_cast<__half*>(base + (n) * BPITCH + (s) * 2) = \
            __float2half_rn(val)
        BST(f,      c,      a1);  BST(f,      12 + c, a1);   // den1:  E *A1
        BST(16 + f, 3 + c,  a1);  BST(16 + f, 15 + c, a1);   // num1: PE *A1
        BST(16 + f, c,      b1);  BST(16 + f, 12 + c, b1);   // num1:  E *B1
        BST(32 + f, 6 + c,  a2);  BST(32 + f, 18 + c, a2);   // den2: EM *A2
        BST(48 + f, 9 + c,  a2);  BST(48 + f, 21 + c, a2);   // num2: PEM*A2
        BST(48 + f, 6 + c,  b2);  BST(48 + f, 18 + c, b2);   // num2: EM *B2
#undef BST
    }
    __syncthreads();

    // ---- Main: 9 taps x 2 k-chunks x (2 m-chunks x 8 n-chunks) MMAs -------
    const uint32_t aBase = smem_u32(smA);
    const uint32_t bBase = smem_u32(smB);
    const int j = lane >> 3, r = lane & 7;
    // A ldmatrix lane addr: matrix j: px += (j&1)*8 + r ; k-bytes += (j>>1)*16
    const uint32_t aLane = aBase + (uint32_t)(((j & 1) * 8 + r) * APITCH +
                                              (j >> 1) * 16);
    // B ldmatrix lane addr: matrix j: n = (j>>1)*8 + r ; k-bytes += (j&1)*16
    const uint32_t bLane = bBase + (uint32_t)(((j >> 1) * 8 + r) * BPITCH +
                                              (j & 1) * 16);
    const uint32_t mOff0 = (uint32_t)((wid * 2) * 16 * APITCH);
    const uint32_t mOff1 = mOff0 + (uint32_t)(16 * APITCH);

    float d[2][8][4];
#pragma unroll
    for (int mc = 0; mc < 2; mc++)
#pragma unroll
        for (int nc = 0; nc < 8; nc++)
#pragma unroll
            for (int q = 0; q < 4; q++) d[mc][nc][q] = 0.0f;

#pragma unroll 1
    for (int tap = 0; tap < 9; tap++) {
        const int kh = tap / 3, kw = tap - kh * 3;
        const uint32_t aTap = aLane + (uint32_t)((kh * 128 + kw) * APITCH);
        const uint32_t bTap = bLane + (uint32_t)(tap * B_TAP);
#pragma unroll
        for (int kc = 0; kc < 2; kc++) {
            uint32_t bf[8][2];
#pragma unroll
            for (int q = 0; q < 4; q++) {
                uint32_t rg[4];
                ldm4(rg, bTap + (uint32_t)(kc * 32 + q * 16 * BPITCH));
                bf[2 * q][0] = rg[0]; bf[2 * q][1] = rg[1];
                bf[2 * q + 1][0] = rg[2]; bf[2 * q + 1][1] = rg[3];
            }
            uint32_t af0[4], af1[4];
            ldm4(af0, aTap + mOff0 + (uint32_t)(kc * 32));
            ldm4(af1, aTap + mOff1 + (uint32_t)(kc * 32));
#pragma unroll
            for (int nc = 0; nc < 8; nc++) mma16816(d[0][nc], af0, bf[nc]);
#pragma unroll
            for (int nc = 0; nc < 8; nc++) mma16816(d[1][nc], af1, bf[nc]);
        }
    }

    // ---- Epilogue: den/num for a given f sit in the SAME lane -------------
    // D frag: c[2h],c[2h+1] = row (lane>>2)+8h, cols (lane&3)*2 + {0,1}
#pragma unroll
    for (int mc = 0; mc < 2; mc++) {
        const int mch = wid * 2 + mc;
#pragma unroll
        for (int h = 0; h < 2; h++) {
            const int mrow = mch * 16 + (lane >> 2) + h * 8;
            const int xc = mrow & 127;
            const int oh = r0 + (mrow >> 7);
            if (xc < WOUT) {
#pragma unroll
                for (int g = 0; g < 2; g++) {
                    const int f = g * 8 + (lane & 3) * 2;
                    const float y0 =
                        __fdividef(d[mc][g + 2][2 * h], d[mc][g][2 * h]) +
                        __fdividef(d[mc][g + 6][2 * h], d[mc][g + 4][2 * h]) +
                        bias[f];
                    const float y1 =
                        __fdividef(d[mc][g + 2][2 * h + 1], d[mc][g][2 * h + 1]) +
                        __fdividef(d[mc][g + 6][2 * h + 1], d[mc][g + 4][2 * h + 1]) +
                        bias[f + 1];
                    out[((b * FOUT + f) * HOUT + oh) * WOUT + xc] = y0;
                    out[((b * FOUT + f + 1) * HOUT + oh) * WOUT + xc] = y1;
                }
            }
        }
    }
}

extern "C" void kernel_launch(void* const* d_in, const int* in_sizes, int n_in,
                              void* d_out, int out_size)
{
    const float* x    = (const float*)d_in[0];
    const float* k1   = (const float*)d_in[1];
    const float* k2   = (const float*)d_in[2];
    const float* bias = (const float*)d_in[3];
    float* out = (float*)d_out;

    // Idempotent, capture-safe (not a stream op); no static guard per
    // harness rules.
    cudaFuncSetAttribute(smorph_hmma_kernel,
                         cudaFuncAttributeMaxDynamicSharedMemorySize,
                         SMEM_DYN);

    dim3 grid(BATCH, HOUT / ROWS_OUT);   // (8, 63)
    smorph_hmma_kernel<<<grid, NT, SMEM_DYN>>>(x, k1, k2, bias, out);
}

// round 13
// speedup vs baseline: 1.6410x; 1.4359x over previous
#include <cuda_runtime.h>
#include <cuda_fp16.h>
#include <cstdint>

// SMorph layer on HMMA (mma.sync m16n8k16 f16->f32), plain sm_100 target.
// Factorized via exp(p+k)=exp(p)exp(k):
//   den1=conv(E,A1)  num1=conv(PE,A1)+conv(E,B1)   (A=exp(k), B=k exp(k))
//   den2=conv(EM,A2) num2=conv(PEM,A2)+conv(EM,B2)
//   out = num1/den1 + num2/den2 + bias
// GEMM: D[m=pixel][n=0..63] ; n: [0,16)=den1, [16,32)=num1, [32,48)=den2,
// [48,64)=num2. K per tap = 16 slots: 0-11 = maps (E,PE,EM,PEM x 3c) in
// fp16, 12-15 zero pad. (Round 12's hi/lo data split measured rel_err
// 4.4e-5, weight-fp16 dominated -> lo half dropped, halving MMA work.)
// 9 taps = 9 accumulating MMA groups whose A base address is shifted by
// (kh*128+kw) pixels (map rows are full-width 128 px).
//
// A smem: pixel-major, 48 B/pixel. 8 rows at 48-B stride hit offsets
// {0,48,96,16,64,112,32,80} mod 128 -> all eight 16-B banks, conflict-free
// ldmatrix. Only bytes 0-31 (k slots 0-15) are ever read.
// B smem: [tap][n][k] rows of 48 B, non-trans ldmatrix = b-fragment direct.

#define BATCH 8
#define CIN   3
#define HIN   128
#define WIN   128
#define FOUT  16
#define HOUT  126
#define WOUT  126

#define NT       256
#define ROWS_OUT 2
#define NPX      (4 * 128 + 8)      // 4 input rows + shift-overflow pad = 520
#define APITCH   48                 // bytes per pixel (16 k-halves + pad)
#define A_BYTES  (NPX * APITCH)     // 24960
#define BPITCH   48                 // bytes per n-row
#define B_TAP    (64 * BPITCH)      // 3072
#define B_BYTES  (9 * B_TAP)        // 27648
#define SMEM_DYN (A_BYTES + B_BYTES)

__device__ __forceinline__ uint32_t smem_u32(const void* p) {
    uint32_t a;
    asm("{ .reg .u64 t; cvta.to.shared.u64 t, %1; cvt.u32.u64 %0, t; }"
        : "=r"(a) : "l"(p));
    return a;
}

__device__ __forceinline__ void ldm4(uint32_t* r, uint32_t addr) {
    asm volatile("ldmatrix.sync.aligned.m8n8.x4.shared.b16 {%0,%1,%2,%3}, [%4];"
                 : "=r"(r[0]), "=r"(r[1]), "=r"(r[2]), "=r"(r[3]) : "r"(addr));
}

__device__ __forceinline__ void mma16816(float* d, const uint32_t* a,
                                         const uint32_t* b) {
    asm volatile(
        "mma.sync.aligned.m16n8k16.row.col.f32.f16.f16.f32 "
        "{%0,%1,%2,%3}, {%4,%5,%6,%7}, {%8,%9}, {%0,%1,%2,%3};"
        : "+f"(d[0]), "+f"(d[1]), "+f"(d[2]), "+f"(d[3])
        : "r"(a[0]), "r"(a[1]), "r"(a[2]), "r"(a[3]), "r"(b[0]), "r"(b[1]));
}

__device__ __forceinline__ uint32_t pkh(__half a, __half b) {
    __half2 h = __halves2half2(a, b);
    return *reinterpret_cast<uint32_t*>(&h);
}

__global__ __launch_bounds__(NT)
void smorph_hmma_kernel(const float* __restrict__ x,
                        const float* __restrict__ k1,
                        const float* __restrict__ k2,
                        const float* __restrict__ bias,
                        float* __restrict__ out)
{
    extern __shared__ char dsm[];
    char* smA = dsm;
    char* smB = dsm + A_BYTES;

    const int tid  = threadIdx.x;
    const int wid  = tid >> 5;
    const int lane = tid & 31;
    const int b    = blockIdx.x;
    const int r0   = blockIdx.y * ROWS_OUT;   // first output row (gy0 too)

    // ---- Phase 1: A map fill (fp16) + B zero ------------------------------
    for (int px = tid; px < NPX; px += NT) {
        float m[12];
#pragma unroll
        for (int i = 0; i < 12; i++) m[i] = 0.0f;
        if (px < 512) {
            int row = px >> 7, xc = px & 127;
            int gy = r0 + row;                 // r0<=124 -> gy<=127, in-bounds
#pragma unroll
            for (int c = 0; c < CIN; c++) {
                float v  = x[((b * CIN + c) * HIN + gy) * WIN + xc];
                float e  = __expf(v);
                float em = __expf(-v);
                m[c]     = e;
                m[3 + c] = v * e;
                m[6 + c] = em;
                m[9 + c] = -v * em;
            }
        }
        uint32_t w[8];
#pragma unroll
        for (int j2 = 0; j2 < 6; j2++)
            w[j2] = pkh(__float2half_rn(m[2 * j2]), __float2half_rn(m[2 * j2 + 1]));
        w[6] = 0u; w[7] = 0u;                  // k slots 12-15 zero
        uint4* dst = reinterpret_cast<uint4*>(smA + px * APITCH);
        dst[0] = make_uint4(w[0], w[1], w[2], w[3]);
        dst[1] = make_uint4(w[4], w[5], w[6], w[7]);
        // bytes 32-47 (pad) never read by ldmatrix; leave as-is
    }
    for (int i = tid; i < B_BYTES / 16; i += NT)
        reinterpret_cast<uint4*>(smB)[i] = make_uint4(0, 0, 0, 0);
    __syncthreads();

    // ---- Phase 2: B weight scatter. k-mem idx ((kh*3+kw)*3+c)*16+f --------
    for (int i = tid; i < 9 * CIN * FOUT; i += NT) {
        int f = i & 15, rest = i >> 4;       // rest = tap*3 + c
        int tap = rest / 3, c = rest - tap * 3;
        int gi = (tap * 3 + c) * FOUT + f;
        float w1 = k1[gi], w2 = k2[gi];
        float a1 = __expf(w1), a2 = __expf(w2);
        float b1 = w1 * a1,   b2 = w2 * a2;
        char* base = smB + tap * B_TAP;
#define BST(n, s, val) \
        *reinterpret_cast<__half*>(base + (n) * BPITCH + (s) * 2) = \
            __float2half_rn(val)
        BST(f,      c,     a1);     // den1:  E  * A1
        BST(16 + f, 3 + c, a1);     // num1:  PE * A1
        BST(16 + f, c,     b1);     // num1:  E  * B1
        BST(32 + f, 6 + c, a2);     // den2:  EM * A2
        BST(48 + f, 9 + c, a2);     // num2: PEM * A2
        BST(48 + f, 6 + c, b2);     // num2:  EM * B2
#undef BST
    }
    __syncthreads();

    // ---- Main: 9 taps x (2 m-chunks x 8 n-chunks) MMAs --------------------
    const uint32_t aBase = smem_u32(smA);
    const uint32_t bBase = smem_u32(smB);
    const int j = lane >> 3, r = lane & 7;
    // A ldmatrix lane addr: matrix j: px += (j&1)*8 + r ; k-bytes += (j>>1)*16
    const uint32_t aLane = aBase + (uint32_t)(((j & 1) * 8 + r) * APITCH +
                                              (j >> 1) * 16);
    // B ldmatrix lane addr: matrix j: n = (j>>1)*8 + r ; k-bytes += (j&1)*16
    const uint32_t bLane = bBase + (uint32_t)(((j >> 1) * 8 + r) * BPITCH +
                                              (j & 1) * 16);
    const uint32_t mOff0 = (uint32_t)((wid * 2) * 16 * APITCH);
    const uint32_t mOff1 = mOff0 + (uint32_t)(16 * APITCH);

    float d[2][8][4];
#pragma unroll
    for (int mc = 0; mc < 2; mc++)
#pragma unroll
        for (int nc = 0; nc < 8; nc++)
#pragma unroll
            for (int q = 0; q < 4; q++) d[mc][nc][q] = 0.0f;

#pragma unroll 1
    for (int tap = 0; tap < 9; tap++) {
        const int kh = tap / 3, kw = tap - kh * 3;
        const uint32_t aTap = aLane + (uint32_t)((kh * 128 + kw) * APITCH);
        const uint32_t bTap = bLane + (uint32_t)(tap * B_TAP);

        uint32_t bf[8][2];
#pragma unroll
        for (int q = 0; q < 4; q++) {
            uint32_t rg[4];
            ldm4(rg, bTap + (uint32_t)(q * 16 * BPITCH));
            bf[2 * q][0] = rg[0]; bf[2 * q][1] = rg[1];
            bf[2 * q + 1][0] = rg[2]; bf[2 * q + 1][1] = rg[3];
        }
        uint32_t af0[4], af1[4];
        ldm4(af0, aTap + mOff0);
        ldm4(af1, aTap + mOff1);
#pragma unroll
        for (int nc = 0; nc < 8; nc++) mma16816(d[0][nc], af0, bf[nc]);
#pragma unroll
        for (int nc = 0; nc < 8; nc++) mma16816(d[1][nc], af1, bf[nc]);
    }

    // ---- Epilogue: den/num for a given f sit in the SAME lane -------------
    // D frag: c[2h],c[2h+1] = row (lane>>2)+8h, cols (lane&3)*2 + {0,1}
#pragma unroll
    for (int mc = 0; mc < 2; mc++) {
        const int mch = wid * 2 + mc;
#pragma unroll
        for (int h = 0; h < 2; h++) {
            const int mrow = mch * 16 + (lane >> 2) + h * 8;
            const int xc = mrow & 127;
            const int oh = r0 + (mrow >> 7);
            if (xc < WOUT) {
#pragma unroll
                for (int g = 0; g < 2; g++) {
                    const int f = g * 8 + (lane & 3) * 2;
                    const float y0 =
                        __fdividef(d[mc][g + 2][2 * h], d[mc][g][2 * h]) +
                        __fdividef(d[mc][g + 6][2 * h], d[mc][g + 4][2 * h]) +
                        bias[f];
                    const float y1 =
                        __fdividef(d[mc][g + 2][2 * h + 1], d[mc][g][2 * h + 1]) +
                        __fdividef(d[mc][g + 6][2 * h + 1], d[mc][g + 4][2 * h + 1]) +
                        bias[f + 1];
                    out[((b * FOUT + f) * HOUT + oh) * WOUT + xc] = y0;
                    out[((b * FOUT + f + 1) * HOUT + oh) * WOUT + xc] = y1;
                }
            }
        }
    }
}

extern "C" void kernel_launch(void* const* d_in, const int* in_sizes, int n_in,
                              void* d_out, int out_size)
{
    const float* x    = (const float*)d_in[0];
    const float* k1   = (const float*)d_in[1];
    const float* k2   = (const float*)d_in[2];
    const float* bias = (const float*)d_in[3];
    float* out = (float*)d_out;

    cudaFuncSetAttribute(smorph_hmma_kernel,
                         cudaFuncAttributeMaxDynamicSharedMemorySize,
                         SMEM_DYN);

    dim3 grid(BATCH, HOUT / ROWS_OUT);   // (8, 63)
    smorph_hmma_kernel<<<grid, NT, SMEM_DYN>>>(x, k1, k2, bias, out);
}